// round 15
// baseline (speedup 1.0000x reference)
#include <cuda_runtime.h>
#include <cuda_bf16.h>
#include <cstdint>

// CombPool2d: out = (w_avg^2)*avg_pool2x2(x) + (w_max^2)*max_pool2x2(x)
// x: (16, 192, 224, 224) fp32 ; w_avg, w_max: (1,192,1,1) ; out: (16,192,112,112)
//
// Best-measured R10 layout (4 output pixels/thread, 2x float4 per source row,
// one STG.128) with the launch made EXACT:
//   3072 planes * 3136 quads = 9,633,792 threads = 37,632 blocks x 256
//   -> no bounds guard, no predicated-off threads (R10 wasted 4.7%).
// Loads: 4 independent LDG.128 (MLP=4), lane stride 32B (8 lines/wavefront,
// measured best DRAM% of all variants). Store: single fully-vectorized STG.128.

#define C_DIM       192
#define H_IN        224
#define W_IN        224
#define H_OUT       112
#define W_OUT       112
#define QUADS_W     (W_OUT / 4)            // 28 float4 outputs per row
#define QUADS_PLANE (H_OUT * QUADS_W)      // 3136 quads per (b,c) plane
#define THREADS     256

__global__ __launch_bounds__(THREADS)
void combpool2d_kernel(const float* __restrict__ x,
                       const float* __restrict__ w_avg,
                       const float* __restrict__ w_max,
                       float* __restrict__ out)
{
    const unsigned idx = blockIdx.x * THREADS + threadIdx.x;  // global quad index

    const unsigned bc  = idx / QUADS_PLANE;                   // plane 0..3071
    const unsigned rem = idx % QUADS_PLANE;
    const unsigned hp  = rem / QUADS_W;                       // output row 0..111
    const unsigned wq  = rem % QUADS_W;                       // float4 col 0..27
    const unsigned c   = bc % C_DIM;

    // Input rows 2hp and 2hp+1; row stride 224 floats = 896 B (16B-aligned).
    const size_t in_plane = (size_t)bc * (H_IN * W_IN);
    const float4* r0 = reinterpret_cast<const float4*>(x + in_plane + (size_t)(2 * hp)     * W_IN) + 2 * wq;
    const float4* r1 = reinterpret_cast<const float4*>(x + in_plane + (size_t)(2 * hp + 1) * W_IN) + 2 * wq;

    // Four independent 128-bit streaming loads (front-batched, MLP=4).
    const float4 a0 = __ldcs(r0);
    const float4 a1 = __ldcs(r0 + 1);
    const float4 b0 = __ldcs(r1);
    const float4 b1 = __ldcs(r1 + 1);

    float ca = __ldg(w_avg + c); ca *= ca;
    float cm = __ldg(w_max + c); cm *= cm;

    // 4 output pixels from windows:
    //  {a0.x,a0.y,b0.x,b0.y}, {a0.z,a0.w,b0.z,b0.w},
    //  {a1.x,a1.y,b1.x,b1.y}, {a1.z,a1.w,b1.z,b1.w}
    const float avg0 = (a0.x + a0.y + b0.x + b0.y) * 0.25f;
    const float mx0  = fmaxf(fmaxf(a0.x, a0.y), fmaxf(b0.x, b0.y));
    const float avg1 = (a0.z + a0.w + b0.z + b0.w) * 0.25f;
    const float mx1  = fmaxf(fmaxf(a0.z, a0.w), fmaxf(b0.z, b0.w));
    const float avg2 = (a1.x + a1.y + b1.x + b1.y) * 0.25f;
    const float mx2  = fmaxf(fmaxf(a1.x, a1.y), fmaxf(b1.x, b1.y));
    const float avg3 = (a1.z + a1.w + b1.z + b1.w) * 0.25f;
    const float mx3  = fmaxf(fmaxf(a1.z, a1.w), fmaxf(b1.z, b1.w));

    float4 o;
    o.x = fmaf(ca, avg0, cm * mx0);
    o.y = fmaf(ca, avg1, cm * mx1);
    o.z = fmaf(ca, avg2, cm * mx2);
    o.w = fmaf(ca, avg3, cm * mx3);

    const size_t out_plane = (size_t)bc * (H_OUT * W_OUT);
    __stcs(reinterpret_cast<float4*>(out + out_plane + (size_t)hp * W_OUT) + wq, o);
}

extern "C" void kernel_launch(void* const* d_in, const int* in_sizes, int n_in,
                              void* d_out, int out_size)
{
    const float* x     = (const float*)d_in[0];
    const float* w_avg = (const float*)d_in[1];
    const float* w_max = (const float*)d_in[2];
    float* out = (float*)d_out;

    const int num_planes = in_sizes[0] / (H_IN * W_IN);        // 3072
    const unsigned total = (unsigned)num_planes * QUADS_PLANE; // 9,633,792
    const unsigned blocks = total / THREADS;                   // exact: 37,632

    combpool2d_kernel<<<blocks, THREADS>>>(x, w_avg, w_max, out);
}

// round 17
// speedup vs baseline: 1.0003x; 1.0003x over previous
#include <cuda_runtime.h>
#include <cuda_bf16.h>
#include <cstdint>

// CombPool2d: out = (w_avg^2)*avg_pool2x2(x) + (w_max^2)*max_pool2x2(x)
// x: (16, 192, 224, 224) fp32 ; w_avg, w_max: (1,192,1,1) ; out: (16,192,112,112)
//
// R15 layout (4 output pixels/thread, exact grid, STG.128 store) with the two
// LDG.128-per-row replaced by ONE 256-bit load per row (sm_100+ ld.global.v8.f32):
//   - lane stride == access width (32 B) -> each warp-wide load covers 1024 B
//     fully dense in a single L1tex wavefront (R15 needed two half-density
//     wavefronts per row).
//   - 2 independent LDG.256 per thread; same 64 B/thread in flight as before.
// All load addresses 32B-aligned: plane stride 200704 B, row stride 896 B,
// column step 32 B. Grid exact: 3072*3136 quads = 37,632 blocks x 256, no tail.

#define C_DIM       192
#define H_IN        224
#define W_IN        224
#define H_OUT       112
#define W_OUT       112
#define QUADS_W     (W_OUT / 4)            // 28 float4 outputs per row
#define QUADS_PLANE (H_OUT * QUADS_W)      // 3136 quads per (b,c) plane
#define THREADS     256

// 256-bit streaming global load (sm_100+/sm_103a). 32B-aligned address required.
__device__ __forceinline__ void ldg256_cs(const float* p, float4& lo, float4& hi)
{
    asm("ld.global.cs.v8.f32 {%0,%1,%2,%3,%4,%5,%6,%7}, [%8];"
        : "=f"(lo.x), "=f"(lo.y), "=f"(lo.z), "=f"(lo.w),
          "=f"(hi.x), "=f"(hi.y), "=f"(hi.z), "=f"(hi.w)
        : "l"(p));
}

__global__ __launch_bounds__(THREADS)
void combpool2d_kernel(const float* __restrict__ x,
                       const float* __restrict__ w_avg,
                       const float* __restrict__ w_max,
                       float* __restrict__ out)
{
    const unsigned idx = blockIdx.x * THREADS + threadIdx.x;  // global quad index

    const unsigned bc  = idx / QUADS_PLANE;                   // plane 0..3071
    const unsigned rem = idx % QUADS_PLANE;
    const unsigned hp  = rem / QUADS_W;                       // output row 0..111
    const unsigned wq  = rem % QUADS_W;                       // 32B col 0..27
    const unsigned c   = bc % C_DIM;

    // Input rows 2hp and 2hp+1 at 8-float column 8*wq.
    const size_t in_plane = (size_t)bc * (H_IN * W_IN);
    const float* r0 = x + in_plane + (size_t)(2 * hp) * W_IN + 8 * wq;

    // Two independent 256-bit streaming loads (rows 2hp, 2hp+1).
    float4 a0, a1, b0, b1;
    ldg256_cs(r0,        a0, a1);
    ldg256_cs(r0 + W_IN, b0, b1);

    float ca = __ldg(w_avg + c); ca *= ca;
    float cm = __ldg(w_max + c); cm *= cm;

    // 4 output pixels from windows:
    //  {a0.x,a0.y,b0.x,b0.y}, {a0.z,a0.w,b0.z,b0.w},
    //  {a1.x,a1.y,b1.x,b1.y}, {a1.z,a1.w,b1.z,b1.w}
    const float avg0 = (a0.x + a0.y + b0.x + b0.y) * 0.25f;
    const float mx0  = fmaxf(fmaxf(a0.x, a0.y), fmaxf(b0.x, b0.y));
    const float avg1 = (a0.z + a0.w + b0.z + b0.w) * 0.25f;
    const float mx1  = fmaxf(fmaxf(a0.z, a0.w), fmaxf(b0.z, b0.w));
    const float avg2 = (a1.x + a1.y + b1.x + b1.y) * 0.25f;
    const float mx2  = fmaxf(fmaxf(a1.x, a1.y), fmaxf(b1.x, b1.y));
    const float avg3 = (a1.z + a1.w + b1.z + b1.w) * 0.25f;
    const float mx3  = fmaxf(fmaxf(a1.z, a1.w), fmaxf(b1.z, b1.w));

    float4 o;
    o.x = fmaf(ca, avg0, cm * mx0);
    o.y = fmaf(ca, avg1, cm * mx1);
    o.z = fmaf(ca, avg2, cm * mx2);
    o.w = fmaf(ca, avg3, cm * mx3);

    const size_t out_plane = (size_t)bc * (H_OUT * W_OUT);
    __stcs(reinterpret_cast<float4*>(out + out_plane + (size_t)hp * W_OUT) + wq, o);
}

extern "C" void kernel_launch(void* const* d_in, const int* in_sizes, int n_in,
                              void* d_out, int out_size)
{
    const float* x     = (const float*)d_in[0];
    const float* w_avg = (const float*)d_in[1];
    const float* w_max = (const float*)d_in[2];
    float* out = (float*)d_out;

    const int num_planes = in_sizes[0] / (H_IN * W_IN);        // 3072
    const unsigned total = (unsigned)num_planes * QUADS_PLANE; // 9,633,792
    const unsigned blocks = total / THREADS;                   // exact: 37,632

    combpool2d_kernel<<<blocks, THREADS>>>(x, w_avg, w_max, out);
}